// round 10
// baseline (speedup 1.0000x reference)
#include <cuda_runtime.h>
#include <cuda_bf16.h>
#include <cstdint>
#include <math.h>

// ---------------------------------------------------------------------------
// EncoderBlock on GB300 (generic-PTX build):
//   GEMMs: bf16 hi*hi (mma.sync.m16n8k16) + fp8 cross terms
//          (mma.sync.m16n8k32.e4m3, operands scaled by 2^14, second accum).
//   Attention: fp32 flash with f32x2 FFMA, vectorized PV.
// ---------------------------------------------------------------------------

#define TOKENS   16384
#define DIM      768
#define HEADS    12
#define HEAD_DIM 64
#define HIDDEN   3072
#define QKV_N    2304
#define LN_EPS   1e-5f
#define CROSS_SCALE    16384.0f
#define CROSS_INV      6.103515625e-05f   // 2^-14

typedef __nv_bfloat16 bf16;

extern __shared__ __align__(1024) char eb_smem_raw[];

// ----------------------------- scratch (device globals) --------------------
__device__ __align__(256) float   g_qkv [TOKENS * QKV_N];
__device__ __align__(256) float   g_xa  [TOKENS * DIM];
__device__ __align__(256) float   g_ffin[TOKENS * DIM];
__device__ __align__(256) float   g_xmlp[TOKENS * DIM];
__device__ __align__(256) bf16    g_bh  [TOKENS * DIM];     // 768-wide act hi
__device__ __align__(256) uint8_t g_b8h [TOKENS * DIM];     // fp8(act)
__device__ __align__(256) uint8_t g_b8l [TOKENS * DIM];     // fp8(2^14*lo)
__device__ __align__(256) bf16    g_ah  [TOKENS * HIDDEN];  // hidden hi
__device__ __align__(256) uint8_t g_h8h [TOKENS * HIDDEN];
__device__ __align__(256) uint8_t g_h8l [TOKENS * HIDDEN];
__device__ __align__(256) bf16    g_wh  [HIDDEN * DIM];     // weight^T hi
__device__ __align__(256) uint8_t g_w8h [HIDDEN * DIM];
__device__ __align__(256) uint8_t g_w8l [HIDDEN * DIM];

// ----------------------------- helpers -------------------------------------
__device__ __forceinline__ uint32_t smem_u32(const void* p) {
    uint32_t a;
    asm("{ .reg .u64 t; cvta.to.shared.u64 t, %1; cvt.u32.u64 %0, t; }"
        : "=r"(a) : "l"(p));
    return a;
}
__device__ __forceinline__ void ldsm4(uint32_t* r, uint32_t addr) {
    asm volatile("ldmatrix.sync.aligned.m8n8.x4.shared.b16 {%0,%1,%2,%3}, [%4];"
                 : "=r"(r[0]), "=r"(r[1]), "=r"(r[2]), "=r"(r[3]) : "r"(addr));
}
__device__ __forceinline__ void mma16816(float* d, const uint32_t* a,
                                         uint32_t b0, uint32_t b1) {
    asm volatile(
        "mma.sync.aligned.m16n8k16.row.col.f32.bf16.bf16.f32 "
        "{%0,%1,%2,%3}, {%4,%5,%6,%7}, {%8,%9}, {%0,%1,%2,%3};"
        : "+f"(d[0]), "+f"(d[1]), "+f"(d[2]), "+f"(d[3])
        : "r"(a[0]), "r"(a[1]), "r"(a[2]), "r"(a[3]), "r"(b0), "r"(b1));
}
__device__ __forceinline__ void mmafp8(float* d, const uint32_t* a,
                                       uint32_t b0, uint32_t b1) {
    asm volatile(
        "mma.sync.aligned.m16n8k32.row.col.f32.e4m3.e4m3.f32 "
        "{%0,%1,%2,%3}, {%4,%5,%6,%7}, {%8,%9}, {%0,%1,%2,%3};"
        : "+f"(d[0]), "+f"(d[1]), "+f"(d[2]), "+f"(d[3])
        : "r"(a[0]), "r"(a[1]), "r"(a[2]), "r"(a[3]), "r"(b0), "r"(b1));
}
#define CP16(dst, src) \
    asm volatile("cp.async.cg.shared.global [%0], [%1], 16;" \
                 :: "r"(dst), "l"(src) : "memory")
#define CP_COMMIT() asm volatile("cp.async.commit_group;" ::: "memory")
template <int N>
__device__ __forceinline__ void cp_wait() {
    asm volatile("cp.async.wait_group %0;" :: "n"(N) : "memory");
}

// ---- f32x2 packed fp32 ----
__device__ __forceinline__ unsigned long long frep2(float a) {
    unsigned long long r;
    unsigned ia = __float_as_uint(a);
    asm("mov.b64 %0, {%1,%2};" : "=l"(r) : "r"(ia), "r"(ia));
    return r;
}
__device__ __forceinline__ void ffma2(unsigned long long& d,
                                      unsigned long long a,
                                      unsigned long long b) {
    asm("fma.rn.f32x2 %0, %1, %2, %0;" : "+l"(d) : "l"(a), "l"(b));
}
__device__ __forceinline__ void fmul2(unsigned long long& d,
                                      unsigned long long a) {
    asm("mul.rn.f32x2 %0, %0, %1;" : "+l"(d) : "l"(a));
}
__device__ __forceinline__ float2 funpack2(unsigned long long v) {
    unsigned lo, hi;
    asm("mov.b64 {%0,%1}, %2;" : "=r"(lo), "=r"(hi) : "l"(v));
    return make_float2(__uint_as_float(lo), __uint_as_float(hi));
}

// ---- fp8 conversion (v0 -> low byte) ----
__device__ __forceinline__ uint16_t pack_e4m3x2(float v1, float v0) {
    uint16_t r;
    asm("cvt.rn.satfinite.e4m3x2.f32 %0, %1, %2;" : "=h"(r) : "f"(v1), "f"(v0));
    return r;
}
__device__ __forceinline__ uint8_t to_e4m3(float v) {
    return (uint8_t)(pack_e4m3x2(0.f, v) & 0xFF);
}

__device__ __forceinline__ float gelu_exact(float v) {
    return 0.5f * v * (1.0f + erff(v * 0.70710678118654752f));
}

// write one element's 3 representations
__device__ __forceinline__ void emit3(float v, bf16* ph, uint8_t* p8h,
                                      uint8_t* p8l, size_t idx) {
    bf16 h = __float2bfloat16(v);
    ph[idx]  = h;
    p8h[idx] = to_e4m3(v);
    p8l[idx] = to_e4m3((v - __bfloat162float(h)) * CROSS_SCALE);
}

// ----------------------------- LayerNorm -----------------------------------
// OUT: 0 = fp32 only, 1 = triple only, 2 = both
template <int OUT>
__global__ void eb_ln_kernel(const float* __restrict__ x,
                             const float* __restrict__ g,
                             const float* __restrict__ b,
                             float* __restrict__ y,
                             bf16* __restrict__ yh,
                             uint8_t* __restrict__ y8h,
                             uint8_t* __restrict__ y8l) {
    int row = blockIdx.x;
    const float* xr = x + (size_t)row * DIM;
    int t = threadIdx.x;
    float v0 = xr[t], v1 = xr[t + 256], v2 = xr[t + 512];
    float s = v0 + v1 + v2;
    float q = v0 * v0 + v1 * v1 + v2 * v2;
    #pragma unroll
    for (int m = 16; m > 0; m >>= 1) {
        s += __shfl_xor_sync(0xffffffffu, s, m);
        q += __shfl_xor_sync(0xffffffffu, q, m);
    }
    __shared__ float ss[8], sq[8];
    __shared__ float mean_s, rstd_s;
    int w = t >> 5, lane = t & 31;
    if (lane == 0) { ss[w] = s; sq[w] = q; }
    __syncthreads();
    if (t == 0) {
        float S = 0.f, Q = 0.f;
        #pragma unroll
        for (int i = 0; i < 8; i++) { S += ss[i]; Q += sq[i]; }
        float mean = S * (1.0f / DIM);
        float var  = Q * (1.0f / DIM) - mean * mean;
        mean_s = mean;
        rstd_s = rsqrtf(var + LN_EPS);
    }
    __syncthreads();
    float mean = mean_s, rstd = rstd_s;
    size_t base = (size_t)row * DIM;
    #pragma unroll
    for (int i = 0; i < 3; i++) {
        int c = t + i * 256;
        float v = (i == 0 ? v0 : (i == 1 ? v1 : v2));
        float o = (v - mean) * rstd * g[c] + b[c];
        if (OUT != 1) y[base + c] = o;
        if (OUT != 0) emit3(o, yh, y8h, y8l, base + c);
    }
}

// ----------------------------- weight transpose + split --------------------
__global__ void eb_wsplit_kernel(const float* __restrict__ W,
                                 bf16* __restrict__ th,
                                 uint8_t* __restrict__ t8h,
                                 uint8_t* __restrict__ t8l,
                                 int K, int N) {
    __shared__ float s[32][33];
    int tx = threadIdx.x, ty = threadIdx.y;
    int n0 = blockIdx.x * 32, k0 = blockIdx.y * 32;
    #pragma unroll
    for (int r = 0; r < 4; r++)
        s[ty + 8 * r][tx] = W[(size_t)(k0 + ty + 8 * r) * N + n0 + tx];
    __syncthreads();
    #pragma unroll
    for (int r = 0; r < 4; r++) {
        float v = s[tx][ty + 8 * r];
        size_t idx = (size_t)(n0 + ty + 8 * r) * K + k0 + tx;
        emit3(v, th, t8h, t8l, idx);
    }
}

// ----------------------------- hybrid bf16+fp8 GEMM ------------------------
// D = Ah*Wh (bf16 mma) + 2^-14 * ( fp8(A)*fp8(2^14 Wl) + fp8(2^14 Al)*fp8(W) )
// Tile 128x128x32, 256 thr (2x4 warps, warp tile 64x32), 3-stage cp.async.
// smem tiles per stage: T0 A-hi bf16 | T1 W-hi bf16 | T2 A-cross fp8 | T3 W-cross fp8
// each 128 rows x 64B, chunk-XOR swizzle (c ^= (row>>1)&3).
// EPI: 0 = bias -> fp32; 1 = bias+residual -> fp32; 2 = bias+GELU -> triple
#define OPB   8192
#define BUFB  (4 * OPB)
#define MM_SMEM (3 * BUFB)     // 96 KB

template <int EPI>
__global__ __launch_bounds__(256, 1)
void eb_mma_gemm(const bf16* __restrict__ Ah, const uint8_t* __restrict__ A8h,
                 const uint8_t* __restrict__ A8l,
                 const bf16* __restrict__ Wh, const uint8_t* __restrict__ W8h,
                 const uint8_t* __restrict__ W8l,
                 const float* __restrict__ bias, const float* __restrict__ R,
                 float* __restrict__ Cf, bf16* __restrict__ Ch,
                 uint8_t* __restrict__ C8h, uint8_t* __restrict__ C8l,
                 int K, int N) {
    uint32_t su = smem_u32(eb_smem_raw);
    int tid = threadIdx.x;
    int lane = tid & 31, wid = tid >> 5;
    int wm = wid >> 2, wn = wid & 3;
    int m0 = blockIdx.y * 128, n0 = blockIdx.x * 128;

    // loader geometry: thread -> (row, half); half = 32B = 2 x 16B chunks
    int crow = tid >> 1;
    int half = tid & 1;
    uint32_t sw   = (uint32_t)((crow >> 1) & 3);
    uint32_t rel0 = crow * 64 + (((2 * half)     ^ sw) * 16);
    uint32_t rel1 = crow * 64 + (((2 * half + 1) ^ sw) * 16);
    const bf16*    pAh = Ah + (size_t)(m0 + crow) * K + half * 16;
    const bf16*    pWh = Wh + (size_t)(n0 + crow) * K + half * 16;
    const uint8_t* pAx = (half ? A8l : A8h) + (size_t)(m0 + crow) * K;
    const uint8_t* pWx = (half ? W8h : W8l) + (size_t)(n0 + crow) * K;

    float acc1[4][4][4], acc2[4][4][4];
    #pragma unroll
    for (int i = 0; i < 4; i++)
        #pragma unroll
        for (int j = 0; j < 4; j++)
            #pragma unroll
            for (int r = 0; r < 4; r++) { acc1[i][j][r] = 0.f; acc2[i][j][r] = 0.f; }

    auto issue = [&](int buf, int k0) {
        uint32_t b = su + buf * BUFB;
        CP16(b + rel0,           pAh + k0);
        CP16(b + rel1,           pAh + k0 + 8);
        CP16(b + OPB + rel0,     pWh + k0);
        CP16(b + OPB + rel1,     pWh + k0 + 8);
        CP16(b + 2 * OPB + rel0, pAx + k0);
        CP16(b + 2 * OPB + rel1, pAx + k0 + 16);
        CP16(b + 3 * OPB + rel0, pWx + k0);
        CP16(b + 3 * OPB + rel1, pWx + k0 + 16);
    };

    int lrow = lane & 15;
    int lhalf = lane >> 4;

    int NK = K >> 5;
    issue(0, 0);  CP_COMMIT();
    issue(1, 32); CP_COMMIT();

    for (int kt = 0; kt < NK; kt++) {
        cp_wait<1>();
        __syncthreads();
        uint32_t bb = su + (kt % 3) * BUFB;

        #pragma unroll
        for (int s = 0; s < 2; s++) {
            uint32_t af[4][4], ax[4][4];
            #pragma unroll
            for (int mt = 0; mt < 4; mt++) {
                int r = wm * 64 + mt * 16 + lrow;
                int ch = 2 * s + lhalf;
                uint32_t ad = bb + r * 64 + ((ch ^ ((r >> 1) & 3)) * 16);
                ldsm4(af[mt], ad);
                ldsm4(ax[mt], ad + 2 * OPB);
            }
            uint32_t bwh[2][4], bwx[2][4];
            #pragma unroll
            for (int g = 0; g < 2; g++) {
                int r = wn * 32 + g * 16 + lrow;
                int ch = 2 * s + lhalf;
                uint32_t ad = bb + OPB + r * 64 + ((ch ^ ((r >> 1) & 3)) * 16);
                ldsm4(bwh[g], ad);
                ldsm4(bwx[g], ad + 2 * OPB);
            }
            #pragma unroll
            for (int mt = 0; mt < 4; mt++) {
                #pragma unroll
                for (int nt = 0; nt < 4; nt++) {
                    int g = nt >> 1, sel = nt & 1;
                    mma16816(acc1[mt][nt], af[mt], bwh[g][sel], bwh[g][sel + 2]);
                    mmafp8 (acc2[mt][nt], ax[mt], bwx[g][sel], bwx[g][sel + 2]);
                }
            }
        }
        if (kt + 2 < NK) { issue((kt + 2) % 3, (kt + 2) * 32); CP_COMMIT(); }
    }

    int grp = lane >> 2, qc = (lane & 3) * 2;
    #pragma unroll
    for (int mt = 0; mt < 4; mt++) {
        int row0 = m0 + wm * 64 + mt * 16 + grp;
        #pragma unroll
        for (int nt = 0; nt < 4; nt++) {
            int col = n0 + wn * 32 + nt * 8 + qc;
            float bx = bias[col], by = bias[col + 1];
            #pragma unroll
            for (int hrow = 0; hrow < 2; hrow++) {
                int row = row0 + hrow * 8;
                float vx = acc1[mt][nt][hrow * 2]     + CROSS_INV * acc2[mt][nt][hrow * 2]     + bx;
                float vy = acc1[mt][nt][hrow * 2 + 1] + CROSS_INV * acc2[mt][nt][hrow * 2 + 1] + by;
                size_t idx = (size_t)row * N + col;
                if (EPI == 2) {
                    vx = gelu_exact(vx); vy = gelu_exact(vy);
                    bf16 h0 = __float2bfloat16(vx);
                    bf16 h1 = __float2bfloat16(vy);
                    *(__nv_bfloat162*)(Ch + idx) = __nv_bfloat162(h0, h1);
                    *(uint16_t*)(C8h + idx) = pack_e4m3x2(vy, vx);
                    *(uint16_t*)(C8l + idx) = pack_e4m3x2(
                        (vy - __bfloat162float(h1)) * CROSS_SCALE,
                        (vx - __bfloat162float(h0)) * CROSS_SCALE);
                } else {
                    if (EPI == 1) {
                        float2 rr = *(const float2*)(R + idx);
                        vx += rr.x; vy += rr.y;
                    }
                    *(float2*)(Cf + idx) = make_float2(vx, vy);
                }
            }
        }
    }
}

// ----------------------------- flash attention (fp32, f32x2) ---------------
#define APAD 68
#define ATTN_SMEM (3 * 64 * APAD * 4)

__global__ __launch_bounds__(128, 4)
void eb_attn_kernel(const float* __restrict__ qkv,
                    bf16* __restrict__ ch, uint8_t* __restrict__ c8h,
                    uint8_t* __restrict__ c8l) {
    float* smem = (float*)eb_smem_raw;
    float (*Qt)[APAD] = (float(*)[APAD])(smem);
    float (*KP)[APAD] = (float(*)[APAD])(smem + 64 * APAD);
    float (*Vs)[APAD] = (float(*)[APAD])(smem + 2 * 64 * APAD);

    int tid = threadIdx.x;
    int tx = tid & 15;
    int ty = tid >> 4;
    int bh = blockIdx.y;
    int b = bh / HEADS, h = bh % HEADS;
    int q0 = blockIdx.x * 64;
    size_t rowbase = (size_t)b * 1024;
    const int LD = QKV_N;
    int qoff = h * HEAD_DIM;
    int koff = DIM + h * HEAD_DIM;
    int voff = 2 * DIM + h * HEAD_DIM;

    {
        int r = tid >> 1;
        int cb = (tid & 1) * 32;
        #pragma unroll
        for (int i = 0; i < 8; i++) {
            int c = cb + i * 4;
            float4 v = *(const float4*)&qkv[(rowbase + q0 + r) * LD + qoff + c];
            Qt[c + 0][r] = v.x * 0.125f; Qt[c + 1][r] = v.y * 0.125f;
            Qt[c + 2][r] = v.z * 0.125f; Qt[c + 3][r] = v.w * 0.125f;
        }
    }

    unsigned long long accp[8][2];
    float m_run[8], l_run[8];
    #pragma unroll
    for (int i = 0; i < 8; i++) {
        m_run[i] = -3.0e38f; l_run[i] = 0.f;
        accp[i][0] = 0ull; accp[i][1] = 0ull;
    }

    for (int kt = 0; kt < 16; kt++) {
        int kr0 = kt * 64;
        __syncthreads();
        {
            int r = tid >> 1;
            int cb = (tid & 1) * 32;
            #pragma unroll
            for (int i = 0; i < 8; i++) {
                int c = cb + i * 4;
                float4 v = *(const float4*)&qkv[(rowbase + kr0 + r) * LD + koff + c];
                KP[c + 0][r] = v.x; KP[c + 1][r] = v.y;
                KP[c + 2][r] = v.z; KP[c + 3][r] = v.w;
                float4 w = *(const float4*)&qkv[(rowbase + kr0 + r) * LD + voff + c];
                *(float4*)&Vs[r][c] = w;
            }
        }
        __syncthreads();

        unsigned long long sp[8][2];
        #pragma unroll
        for (int i = 0; i < 8; i++) { sp[i][0] = 0ull; sp[i][1] = 0ull; }
        #pragma unroll 4
        for (int d = 0; d < 64; d++) {
            float4 aA = *(const float4*)&Qt[d][ty * 8];
            float4 aB = *(const float4*)&Qt[d][ty * 8 + 4];
            ulonglong2 bu = *(const ulonglong2*)&KP[d][tx * 4];
            float a[8] = {aA.x, aA.y, aA.z, aA.w, aB.x, aB.y, aB.z, aB.w};
            #pragma unroll
            for (int i = 0; i < 8; i++) {
                unsigned long long ar = frep2(a[i]);
                ffma2(sp[i][0], ar, bu.x);
                ffma2(sp[i][1], ar, bu.y);
            }
        }
        __syncthreads();

        #pragma unroll
        for (int i = 0; i < 8; i++) {
            float2 s01 = funpack2(sp[i][0]);
            float2 s23 = funpack2(sp[i][1]);
            float tm = fmaxf(fmaxf(s01.x, s01.y), fmaxf(s23.x, s23.y));
            tm = fmaxf(tm, __shfl_xor_sync(0xffffffffu, tm, 1));
            tm = fmaxf(tm, __shfl_xor_sync(0xffffffffu, tm, 2));
            tm = fmaxf(tm, __shfl_xor_sync(0xffffffffu, tm, 4));
            tm = fmaxf(tm, __shfl_xor_sync(0xffffffffu, tm, 8));
            float mn = fmaxf(m_run[i], tm);
            float sc = __expf(m_run[i] - mn);
            float p0 = __expf(s01.x - mn), p1 = __expf(s01.y - mn);
            float p2 = __expf(s23.x - mn), p3 = __expf(s23.y - mn);
            float ps = (p0 + p1) + (p2 + p3);
            ps += __shfl_xor_sync(0xffffffffu, ps, 1);
            ps += __shfl_xor_sync(0xffffffffu, ps, 2);
            ps += __shfl_xor_sync(0xffffffffu, ps, 4);
            ps += __shfl_xor_sync(0xffffffffu, ps, 8);
            l_run[i] = l_run[i] * sc + ps;
            m_run[i] = mn;
            unsigned long long scp = frep2(sc);
            fmul2(accp[i][0], scp);
            fmul2(accp[i][1], scp);
            *(float4*)&KP[ty * 8 + i][tx * 4] = make_float4(p0, p1, p2, p3);
        }
        __syncthreads();

        // PV: vectorized P loads (float4 per row per 4-col chunk)
        #pragma unroll 2
        for (int c4 = 0; c4 < 64; c4 += 4) {
            ulonglong2 v0 = *(const ulonglong2*)&Vs[c4 + 0][tx * 4];
            ulonglong2 v1 = *(const ulonglong2*)&Vs[c4 + 1][tx * 4];
            ulonglong2 v2 = *(const ulonglong2*)&Vs[c4 + 2][tx * 4];
            ulonglong2 v3 = *(const ulonglong2*)&Vs[c4 + 3][tx * 4];
            #pragma unroll
            for (int i = 0; i < 8; i++) {
                float4 p = *(const float4*)&KP[ty * 8 + i][c4];
                unsigned long long pr;
                pr = frep2(p.x); ffma2(accp[i][0], pr, v0.x); ffma2(accp[i][1], pr, v0.y);
                pr = frep2(p.y); ffma2(accp[i][0], pr, v1.x); ffma2(accp[i][1], pr, v1.y);
                pr = frep2(p.z); ffma2(accp[i][0], pr, v2.x); ffma2(accp[i][1], pr, v2.y);
                pr = frep2(p.w); ffma2(accp[i][0], pr, v3.x); ffma2(accp[i][1], pr, v3.y);
            }
        }
    }

    #pragma unroll
    for (int i = 0; i < 8; i++) {
        float inv = 1.0f / l_run[i];
        float2 a01 = funpack2(accp[i][0]);
        float2 a23 = funpack2(accp[i][1]);
        size_t idx = (rowbase + q0 + ty * 8 + i) * DIM + h * HEAD_DIM + tx * 4;
        float o0 = a01.x * inv, o1 = a01.y * inv;
        float o2 = a23.x * inv, o3 = a23.y * inv;
        bf16 h0 = __float2bfloat16(o0), h1 = __float2bfloat16(o1);
        bf16 h2 = __float2bfloat16(o2), h3 = __float2bfloat16(o3);
        *(__nv_bfloat162*)(ch + idx)     = __nv_bfloat162(h0, h1);
        *(__nv_bfloat162*)(ch + idx + 2) = __nv_bfloat162(h2, h3);
        *(uint16_t*)(c8h + idx)     = pack_e4m3x2(o1, o0);
        *(uint16_t*)(c8h + idx + 2) = pack_e4m3x2(o3, o2);
        *(uint16_t*)(c8l + idx)     = pack_e4m3x2(
            (o1 - __bfloat162float(h1)) * CROSS_SCALE,
            (o0 - __bfloat162float(h0)) * CROSS_SCALE);
        *(uint16_t*)(c8l + idx + 2) = pack_e4m3x2(
            (o3 - __bfloat162float(h3)) * CROSS_SCALE,
            (o2 - __bfloat162float(h2)) * CROSS_SCALE);
    }
}

// ----------------------------- launch ---------------------------------------
extern "C" void kernel_launch(void* const* d_in, const int* in_sizes, int n_in,
                              void* d_out, int out_size) {
    const float* x      = (const float*)d_in[0];
    const float* ln1_g  = (const float*)d_in[1];
    const float* ln1_b  = (const float*)d_in[2];
    const float* qkv_w  = (const float*)d_in[3];
    const float* qkv_b  = (const float*)d_in[4];
    const float* proj_w = (const float*)d_in[5];
    const float* proj_b = (const float*)d_in[6];
    const float* ln2_g  = (const float*)d_in[7];
    const float* ln2_b  = (const float*)d_in[8];
    const float* fc1_w  = (const float*)d_in[9];
    const float* fc1_b  = (const float*)d_in[10];
    const float* fc2_w  = (const float*)d_in[11];
    const float* fc2_b  = (const float*)d_in[12];
    const float* ln3_g  = (const float*)d_in[13];
    const float* ln3_b  = (const float*)d_in[14];
    float* out = (float*)d_out;

    void *p;
    cudaGetSymbolAddress(&p, g_qkv);  float* qkv  = (float*)p;
    cudaGetSymbolAddress(&p, g_xa);   float* xa   = (float*)p;
    cudaGetSymbolAddress(&p, g_ffin); float* ffin = (float*)p;
    cudaGetSymbolAddress(&p, g_xmlp); float* xmlp = (float*)p;
    cudaGetSymbolAddress(&p, g_bh);   bf16* bh = (bf16*)p;
    cudaGetSymbolAddress(&p, g_b8h);  uint8_t* b8h = (uint8_t*)p;
    cudaGetSymbolAddress(&p, g_b8l);  uint8_t* b8l = (uint8_t*)p;
    cudaGetSymbolAddress(&p, g_ah);   bf16* ah = (bf16*)p;
    cudaGetSymbolAddress(&p, g_h8h);  uint8_t* h8h = (uint8_t*)p;
    cudaGetSymbolAddress(&p, g_h8l);  uint8_t* h8l = (uint8_t*)p;
    cudaGetSymbolAddress(&p, g_wh);   bf16* wh = (bf16*)p;
    cudaGetSymbolAddress(&p, g_w8h);  uint8_t* w8h = (uint8_t*)p;
    cudaGetSymbolAddress(&p, g_w8l);  uint8_t* w8l = (uint8_t*)p;

    cudaFuncSetAttribute(eb_attn_kernel,
                         cudaFuncAttributeMaxDynamicSharedMemorySize, ATTN_SMEM);
    cudaFuncSetAttribute(eb_mma_gemm<0>,
                         cudaFuncAttributeMaxDynamicSharedMemorySize, MM_SMEM);
    cudaFuncSetAttribute(eb_mma_gemm<1>,
                         cudaFuncAttributeMaxDynamicSharedMemorySize, MM_SMEM);
    cudaFuncSetAttribute(eb_mma_gemm<2>,
                         cudaFuncAttributeMaxDynamicSharedMemorySize, MM_SMEM);

    dim3 wsb(32, 8);

    // 1. LN1 -> triple activations
    eb_ln_kernel<1><<<TOKENS, 256>>>(x, ln1_g, ln1_b, nullptr, bh, b8h, b8l);
    // 2. QKV
    eb_wsplit_kernel<<<dim3(QKV_N / 32, DIM / 32), wsb>>>(qkv_w, wh, w8h, w8l, DIM, QKV_N);
    eb_mma_gemm<0><<<dim3(QKV_N / 128, TOKENS / 128), 256, MM_SMEM>>>(
        bh, b8h, b8l, wh, w8h, w8l, qkv_b, nullptr, qkv, nullptr, nullptr, nullptr,
        DIM, QKV_N);
    // 3. attention -> ctx triple
    eb_attn_kernel<<<dim3(1024 / 64, 16 * HEADS), 128, ATTN_SMEM>>>(qkv, bh, b8h, b8l);
    // 4. proj + residual(x)
    eb_wsplit_kernel<<<dim3(DIM / 32, DIM / 32), wsb>>>(proj_w, wh, w8h, w8l, DIM, DIM);
    eb_mma_gemm<1><<<dim3(DIM / 128, TOKENS / 128), 256, MM_SMEM>>>(
        bh, b8h, b8l, wh, w8h, w8l, proj_b, x, xa, nullptr, nullptr, nullptr,
        DIM, DIM);
    // 5. LN2 -> ffin fp32 + triple
    eb_ln_kernel<2><<<TOKENS, 256>>>(xa, ln2_g, ln2_b, ffin, bh, b8h, b8l);
    // 6. fc1 + GELU -> hidden triple
    eb_wsplit_kernel<<<dim3(HIDDEN / 32, DIM / 32), wsb>>>(fc1_w, wh, w8h, w8l, DIM, HIDDEN);
    eb_mma_gemm<2><<<dim3(HIDDEN / 128, TOKENS / 128), 256, MM_SMEM>>>(
        bh, b8h, b8l, wh, w8h, w8l, fc1_b, nullptr, nullptr, ah, h8h, h8l,
        DIM, HIDDEN);
    // 7. fc2 + residual(ffin)
    eb_wsplit_kernel<<<dim3(DIM / 32, HIDDEN / 32), wsb>>>(fc2_w, wh, w8h, w8l, HIDDEN, DIM);
    eb_mma_gemm<1><<<dim3(DIM / 128, TOKENS / 128), 256, MM_SMEM>>>(
        ah, h8h, h8l, wh, w8h, w8l, fc2_b, ffin, xmlp, nullptr, nullptr, nullptr,
        HIDDEN, DIM);
    // 8. LN3 -> out
    eb_ln_kernel<0><<<TOKENS, 256>>>(xmlp, ln3_g, ln3_b, out, nullptr, nullptr, nullptr);
}

// round 12
// speedup vs baseline: 1.5716x; 1.5716x over previous
#include <cuda_runtime.h>
#include <cuda_fp16.h>
#include <cstdint>
#include <math.h>

// ---------------------------------------------------------------------------
// EncoderBlock on GB300 (generic-PTX build):
//   GEMMs: fp16 mma.sync m16n8k16, 2-pass (act single fp16, weight exact
//          fp16 pair Wh+Wl), fp32 accumulate, occ 2, cp.async double buffer.
//   Attention: fp32 flash with f32x2 FFMA.
// (Resubmission of R11 — prior bench lost to container infra failure.)
// ---------------------------------------------------------------------------

#define TOKENS   16384
#define DIM      768
#define HEADS    12
#define HEAD_DIM 64
#define HIDDEN   3072
#define QKV_N    2304
#define LN_EPS   1e-5f

typedef __half f16;

extern __shared__ __align__(1024) char eb_smem_raw[];

// ----------------------------- scratch (device globals) --------------------
__device__ __align__(256) float g_qkv [TOKENS * QKV_N];
__device__ __align__(256) float g_xa  [TOKENS * DIM];
__device__ __align__(256) float g_ffin[TOKENS * DIM];
__device__ __align__(256) float g_xmlp[TOKENS * DIM];
__device__ __align__(256) f16   g_b16 [TOKENS * DIM];     // 768-wide act fp16
__device__ __align__(256) f16   g_h16 [TOKENS * HIDDEN];  // hidden act fp16
__device__ __align__(256) f16   g_w16h[HIDDEN * DIM];     // weight^T fp16 hi
__device__ __align__(256) f16   g_w16l[HIDDEN * DIM];     // weight^T fp16 lo

// ----------------------------- helpers -------------------------------------
__device__ __forceinline__ uint32_t smem_u32(const void* p) {
    uint32_t a;
    asm("{ .reg .u64 t; cvta.to.shared.u64 t, %1; cvt.u32.u64 %0, t; }"
        : "=r"(a) : "l"(p));
    return a;
}
__device__ __forceinline__ void ldsm4(uint32_t* r, uint32_t addr) {
    asm volatile("ldmatrix.sync.aligned.m8n8.x4.shared.b16 {%0,%1,%2,%3}, [%4];"
                 : "=r"(r[0]), "=r"(r[1]), "=r"(r[2]), "=r"(r[3]) : "r"(addr));
}
__device__ __forceinline__ void mma16816(float* d, const uint32_t* a,
                                         uint32_t b0, uint32_t b1) {
    asm volatile(
        "mma.sync.aligned.m16n8k16.row.col.f32.f16.f16.f32 "
        "{%0,%1,%2,%3}, {%4,%5,%6,%7}, {%8,%9}, {%0,%1,%2,%3};"
        : "+f"(d[0]), "+f"(d[1]), "+f"(d[2]), "+f"(d[3])
        : "r"(a[0]), "r"(a[1]), "r"(a[2]), "r"(a[3]), "r"(b0), "r"(b1));
}
#define CP16(dst, src) \
    asm volatile("cp.async.cg.shared.global [%0], [%1], 16;" \
                 :: "r"(dst), "l"(src) : "memory")
#define CP_COMMIT() asm volatile("cp.async.commit_group;" ::: "memory")
template <int N>
__device__ __forceinline__ void cp_wait() {
    asm volatile("cp.async.wait_group %0;" :: "n"(N) : "memory");
}

// ---- f32x2 packed fp32 ----
__device__ __forceinline__ unsigned long long frep2(float a) {
    unsigned long long r;
    unsigned ia = __float_as_uint(a);
    asm("mov.b64 %0, {%1,%2};" : "=l"(r) : "r"(ia), "r"(ia));
    return r;
}
__device__ __forceinline__ void ffma2(unsigned long long& d,
                                      unsigned long long a,
                                      unsigned long long b) {
    asm("fma.rn.f32x2 %0, %1, %2, %0;" : "+l"(d) : "l"(a), "l"(b));
}
__device__ __forceinline__ void fmul2(unsigned long long& d,
                                      unsigned long long a) {
    asm("mul.rn.f32x2 %0, %0, %1;" : "+l"(d) : "l"(a));
}
__device__ __forceinline__ float2 funpack2(unsigned long long v) {
    unsigned lo, hi;
    asm("mov.b64 {%0,%1}, %2;" : "=r"(lo), "=r"(hi) : "l"(v));
    return make_float2(__uint_as_float(lo), __uint_as_float(hi));
}

__device__ __forceinline__ float gelu_exact(float v) {
    return 0.5f * v * (1.0f + erff(v * 0.70710678118654752f));
}

// ----------------------------- LayerNorm -----------------------------------
// OUT: 0 = fp32 only, 1 = fp16 only, 2 = both
template <int OUT>
__global__ void eb_ln_kernel(const float* __restrict__ x,
                             const float* __restrict__ g,
                             const float* __restrict__ b,
                             float* __restrict__ y,
                             f16* __restrict__ y16) {
    int row = blockIdx.x;
    const float* xr = x + (size_t)row * DIM;
    int t = threadIdx.x;
    float v0 = xr[t], v1 = xr[t + 256], v2 = xr[t + 512];
    float s = v0 + v1 + v2;
    float q = v0 * v0 + v1 * v1 + v2 * v2;
    #pragma unroll
    for (int m = 16; m > 0; m >>= 1) {
        s += __shfl_xor_sync(0xffffffffu, s, m);
        q += __shfl_xor_sync(0xffffffffu, q, m);
    }
    __shared__ float ss[8], sq[8];
    __shared__ float mean_s, rstd_s;
    int w = t >> 5, lane = t & 31;
    if (lane == 0) { ss[w] = s; sq[w] = q; }
    __syncthreads();
    if (t == 0) {
        float S = 0.f, Q = 0.f;
        #pragma unroll
        for (int i = 0; i < 8; i++) { S += ss[i]; Q += sq[i]; }
        float mean = S * (1.0f / DIM);
        float var  = Q * (1.0f / DIM) - mean * mean;
        mean_s = mean;
        rstd_s = rsqrtf(var + LN_EPS);
    }
    __syncthreads();
    float mean = mean_s, rstd = rstd_s;
    size_t base = (size_t)row * DIM;
    #pragma unroll
    for (int i = 0; i < 3; i++) {
        int c = t + i * 256;
        float v = (i == 0 ? v0 : (i == 1 ? v1 : v2));
        float o = (v - mean) * rstd * g[c] + b[c];
        if (OUT != 1) y[base + c] = o;
        if (OUT != 0) y16[base + c] = __float2half(o);
    }
}

// ----------------------------- weight transpose + fp16 pair split ----------
// W [K][N] fp32 -> wt hi/lo fp16 [N][K];  Wh + Wl == W to ~2^-21
__global__ void eb_wsplit_kernel(const float* __restrict__ W,
                                 f16* __restrict__ th, f16* __restrict__ tl,
                                 int K, int N) {
    __shared__ float s[32][33];
    int tx = threadIdx.x, ty = threadIdx.y;
    int n0 = blockIdx.x * 32, k0 = blockIdx.y * 32;
    #pragma unroll
    for (int r = 0; r < 4; r++)
        s[ty + 8 * r][tx] = W[(size_t)(k0 + ty + 8 * r) * N + n0 + tx];
    __syncthreads();
    #pragma unroll
    for (int r = 0; r < 4; r++) {
        float v = s[tx][ty + 8 * r];
        size_t idx = (size_t)(n0 + ty + 8 * r) * K + k0 + tx;
        f16 h = __float2half(v);
        th[idx] = h;
        tl[idx] = __float2half(v - __half2float(h));
    }
}

// ----------------------------- fp16 2-pass GEMM ----------------------------
// C[M,N] = epi(A16[m,k] * (Wh+Wl)[n,k] + bias)
// Tile 128x128x32, 256 thr (2x4 warps, warp tile 64x32), cp.async dbl-buffer,
// occ 2. smem/stage: T0 A fp16 | T1 Wh | T2 Wl, each 128 rows x 64B.
// chunk-XOR swizzle (c ^= (row>>1)&3).
// EPI: 0 = bias -> fp32; 1 = bias + residual -> fp32; 2 = bias+GELU -> fp16
#define OPB   8192
#define BUFB  (3 * OPB)
#define MM_SMEM (2 * BUFB)    // 48 KB per CTA

template <int EPI>
__global__ __launch_bounds__(256, 2)
void eb_mma_gemm(const f16* __restrict__ A16,
                 const f16* __restrict__ Wh, const f16* __restrict__ Wl,
                 const float* __restrict__ bias, const float* __restrict__ R,
                 float* __restrict__ Cf, f16* __restrict__ C16,
                 int K, int N) {
    uint32_t su = smem_u32(eb_smem_raw);
    int tid = threadIdx.x;
    int lane = tid & 31, wid = tid >> 5;
    int wm = wid >> 2, wn = wid & 3;
    int m0 = blockIdx.y * 128, n0 = blockIdx.x * 128;

    // loader: thread -> (row, 2 x 16B chunks) per tile
    int crow = tid >> 1;
    int cc0  = (tid & 1) * 2;
    uint32_t sw   = (uint32_t)((crow >> 1) & 3);
    uint32_t rel0 = crow * 64 + ((cc0 ^ sw) * 16);
    uint32_t rel1 = crow * 64 + (((cc0 + 1) ^ sw) * 16);
    const f16* pA  = A16 + (size_t)(m0 + crow) * K + cc0 * 8;
    const f16* pWh = Wh  + (size_t)(n0 + crow) * K + cc0 * 8;
    const f16* pWl = Wl  + (size_t)(n0 + crow) * K + cc0 * 8;

    float acc[4][4][4];
    #pragma unroll
    for (int i = 0; i < 4; i++)
        #pragma unroll
        for (int j = 0; j < 4; j++)
            #pragma unroll
            for (int r = 0; r < 4; r++) acc[i][j][r] = 0.f;

    auto issue = [&](int buf, int koff) {
        uint32_t b = su + buf * BUFB;
        CP16(b + rel0,           pA  + koff);
        CP16(b + rel1,           pA  + koff + 8);
        CP16(b + OPB + rel0,     pWh + koff);
        CP16(b + OPB + rel1,     pWh + koff + 8);
        CP16(b + 2 * OPB + rel0, pWl + koff);
        CP16(b + 2 * OPB + rel1, pWl + koff + 8);
    };

    int lrow = lane & 15;
    int lhalf = lane >> 4;

    int NK = K >> 5;
    issue(0, 0);
    CP_COMMIT();

    for (int kt = 0; kt < NK; kt++) {
        if (kt + 1 < NK) {
            issue((kt + 1) & 1, (kt + 1) * 32);
            CP_COMMIT();
            cp_wait<1>();
        } else {
            cp_wait<0>();
        }
        __syncthreads();
        uint32_t bb = su + (kt & 1) * BUFB;

        #pragma unroll
        for (int s = 0; s < 2; s++) {
            uint32_t af[4][4];
            #pragma unroll
            for (int mt = 0; mt < 4; mt++) {
                int r = wm * 64 + mt * 16 + lrow;
                int ch = 2 * s + lhalf;
                uint32_t ad = bb + r * 64 + ((ch ^ ((r >> 1) & 3)) * 16);
                ldsm4(af[mt], ad);
            }
            uint32_t bh[2][4], bl[2][4];
            #pragma unroll
            for (int g = 0; g < 2; g++) {
                int r = wn * 32 + g * 16 + lrow;
                int ch = 2 * s + lhalf;
                uint32_t ad = bb + OPB + r * 64 + ((ch ^ ((r >> 1) & 3)) * 16);
                ldsm4(bh[g], ad);
                ldsm4(bl[g], ad + OPB);
            }
            #pragma unroll
            for (int mt = 0; mt < 4; mt++) {
                #pragma unroll
                for (int nt = 0; nt < 4; nt++) {
                    int g = nt >> 1, sel = nt & 1;
                    mma16816(acc[mt][nt], af[mt], bh[g][sel], bh[g][sel + 2]);
                    mma16816(acc[mt][nt], af[mt], bl[g][sel], bl[g][sel + 2]);
                }
            }
        }
        __syncthreads();
    }

    int grp = lane >> 2, qc = (lane & 3) * 2;
    #pragma unroll
    for (int mt = 0; mt < 4; mt++) {
        int row0 = m0 + wm * 64 + mt * 16 + grp;
        #pragma unroll
        for (int nt = 0; nt < 4; nt++) {
            int col = n0 + wn * 32 + nt * 8 + qc;
            float bx = bias[col], by = bias[col + 1];
            #pragma unroll
            for (int hrow = 0; hrow < 2; hrow++) {
                int row = row0 + hrow * 8;
                float vx = acc[mt][nt][hrow * 2]     + bx;
                float vy = acc[mt][nt][hrow * 2 + 1] + by;
                size_t idx = (size_t)row * N + col;
                if (EPI == 2) {
                    vx = gelu_exact(vx); vy = gelu_exact(vy);
                    *(__half2*)(C16 + idx) =
                        __halves2half2(__float2half(vx), __float2half(vy));
                } else {
                    if (EPI == 1) {
                        float2 rr = *(const float2*)(R + idx);
                        vx += rr.x; vy += rr.y;
                    }
                    *(float2*)(Cf + idx) = make_float2(vx, vy);
                }
            }
        }
    }
}

// ----------------------------- flash attention (fp32, f32x2) ---------------
#define APAD 68
#define ATTN_SMEM (3 * 64 * APAD * 4)

__global__ __launch_bounds__(128, 4)
void eb_attn_kernel(const float* __restrict__ qkv, f16* __restrict__ c16) {
    float* smem = (float*)eb_smem_raw;
    float (*Qt)[APAD] = (float(*)[APAD])(smem);
    float (*KP)[APAD] = (float(*)[APAD])(smem + 64 * APAD);
    float (*Vs)[APAD] = (float(*)[APAD])(smem + 2 * 64 * APAD);

    int tid = threadIdx.x;
    int tx = tid & 15;
    int ty = tid >> 4;
    int bh = blockIdx.y;
    int b = bh / HEADS, h = bh % HEADS;
    int q0 = blockIdx.x * 64;
    size_t rowbase = (size_t)b * 1024;
    const int LD = QKV_N;
    int qoff = h * HEAD_DIM;
    int koff = DIM + h * HEAD_DIM;
    int voff = 2 * DIM + h * HEAD_DIM;

    {
        int r = tid >> 1;
        int cb = (tid & 1) * 32;
        #pragma unroll
        for (int i = 0; i < 8; i++) {
            int c = cb + i * 4;
            float4 v = *(const float4*)&qkv[(rowbase + q0 + r) * LD + qoff + c];
            Qt[c + 0][r] = v.x * 0.125f; Qt[c + 1][r] = v.y * 0.125f;
            Qt[c + 2][r] = v.z * 0.125f; Qt[c + 3][r] = v.w * 0.125f;
        }
    }

    unsigned long long accp[8][2];
    float m_run[8], l_run[8];
    #pragma unroll
    for (int i = 0; i < 8; i++) {
        m_run[i] = -3.0e38f; l_run[i] = 0.f;
        accp[i][0] = 0ull; accp[i][1] = 0ull;
    }

    for (int kt = 0; kt < 16; kt++) {
        int kr0 = kt * 64;
        __syncthreads();
        {
            int r = tid >> 1;
            int cb = (tid & 1) * 32;
            #pragma unroll
            for (int i = 0; i < 8; i++) {
                int c = cb + i * 4;
                float4 v = *(const float4*)&qkv[(rowbase + kr0 + r) * LD + koff + c];
                KP[c + 0][r] = v.x; KP[c + 1][r] = v.y;
                KP[c + 2][r] = v.z; KP[c + 3][r] = v.w;
                float4 w = *(const float4*)&qkv[(rowbase + kr0 + r) * LD + voff + c];
                *(float4*)&Vs[r][c] = w;
            }
        }
        __syncthreads();

        unsigned long long sp[8][2];
        #pragma unroll
        for (int i = 0; i < 8; i++) { sp[i][0] = 0ull; sp[i][1] = 0ull; }
        #pragma unroll 4
        for (int d = 0; d < 64; d++) {
            float4 aA = *(const float4*)&Qt[d][ty * 8];
            float4 aB = *(const float4*)&Qt[d][ty * 8 + 4];
            ulonglong2 bu = *(const ulonglong2*)&KP[d][tx * 4];
            float a[8] = {aA.x, aA.y, aA.z, aA.w, aB.x, aB.y, aB.z, aB.w};
            #pragma unroll
            for (int i = 0; i < 8; i++) {
                unsigned long long ar = frep2(a[i]);
                ffma2(sp[i][0], ar, bu.x);
                ffma2(sp[i][1], ar, bu.y);
            }
        }
        __syncthreads();

        #pragma unroll
        for (int i = 0; i < 8; i++) {
            float2 s01 = funpack2(sp[i][0]);
            float2 s23 = funpack2(sp[i][1]);
            float tm = fmaxf(fmaxf(s01.x, s01.y), fmaxf(s23.x, s23.y));
            tm = fmaxf(tm, __shfl_xor_sync(0xffffffffu, tm, 1));
            tm = fmaxf(tm, __shfl_xor_sync(0xffffffffu, tm, 2));
            tm = fmaxf(tm, __shfl_xor_sync(0xffffffffu, tm, 4));
            tm = fmaxf(tm, __shfl_xor_sync(0xffffffffu, tm, 8));
            float mn = fmaxf(m_run[i], tm);
            float sc = __expf(m_run[i] - mn);
            float p0 = __expf(s01.x - mn), p1 = __expf(s01.y - mn);
            float p2 = __expf(s23.x - mn), p3 = __expf(s23.y - mn);
            float ps = (p0 + p1) + (p2 + p3);
            ps += __shfl_xor_sync(0xffffffffu, ps, 1);
            ps += __shfl_xor_sync(0xffffffffu, ps, 2);
            ps += __shfl_xor_sync(0xffffffffu, ps, 4);
            ps += __shfl_xor_sync(0xffffffffu, ps, 8);
            l_run[i] = l_run[i] * sc + ps;
            m_run[i] = mn;
            unsigned long long scp = frep2(sc);
            fmul2(accp[i][0], scp);
            fmul2(accp[i][1], scp);
            *(float4*)&KP[ty * 8 + i][tx * 4] = make_float4(p0, p1, p2, p3);
        }
        __syncthreads();

        #pragma unroll 2
        for (int c4 = 0; c4 < 64; c4 += 4) {
            ulonglong2 v0 = *(const ulonglong2*)&Vs[c4 + 0][tx * 4];
            ulonglong2 v1 = *(const ulonglong2*)&Vs[c4 + 1][tx * 4];
            ulonglong2 v2 = *(const ulonglong2*)&Vs[c4 + 2][tx * 4];
            ulonglong2 v3 = *(const ulonglong2*)&Vs[c4 + 3][tx * 4];
            #pragma unroll
            for (int i = 0; i < 8; i++) {
                float4 p = *(const float4*)&KP[ty * 8 + i][c4];
                unsigned long long pr;
                pr = frep2(p.x); ffma2(accp[i][0], pr, v0.x); ffma2(accp[i][1], pr, v0.y);
                pr = frep2(p.y); ffma2(accp[i][0], pr, v1.x); ffma2(accp[i][1], pr, v1.y);
                pr = frep2(p.z); ffma2(accp[i][0], pr, v2.x); ffma2(accp[i][1], pr, v2.y);
                pr = frep2(p.w); ffma2(accp[i][0], pr, v3.x); ffma2(accp[i][1], pr, v3.y);
            }
        }
    }

    #pragma unroll
    for (int i = 0; i < 8; i++) {
        float inv = 1.0f / l_run[i];
        float2 a01 = funpack2(accp[i][0]);
        float2 a23 = funpack2(accp[i][1]);
        size_t idx = (rowbase + q0 + ty * 8 + i) * DIM + h * HEAD_DIM + tx * 4;
        *(__half2*)(c16 + idx) = __halves2half2(
            __float2half(a01.x * inv), __float2half(a01.y * inv));
        *(__half2*)(c16 + idx + 2) = __halves2half2(
            __float2half(a23.x * inv), __float2half(a23.y * inv));
    }
}

// ----------------------------- launch ---------------------------------------
extern "C" void kernel_launch(void* const* d_in, const int* in_sizes, int n_in,
                              void* d_out, int out_size) {
    const float* x      = (const float*)d_in[0];
    const float* ln1_g  = (const float*)d_in[1];
    const float* ln1_b  = (const float*)d_in[2];
    const float* qkv_w  = (const float*)d_in[3];
    const float* qkv_b  = (const float*)d_in[4];
    const float* proj_w = (const float*)d_in[5];
    const float* proj_b = (const float*)d_in[6];
    const float* ln2_g  = (const float*)d_in[7];
    const float* ln2_b  = (const float*)d_in[8];
    const float* fc1_w  = (const float*)d_in[9];
    const float* fc1_b  = (const float*)d_in[10];
    const float* fc2_w  = (const float*)d_in[11];
    const float* fc2_b  = (const float*)d_in[12];
    const float* ln3_g  = (const float*)d_in[13];
    const float* ln3_b  = (const float*)d_in[14];
    float* out = (float*)d_out;

    void *p;
    cudaGetSymbolAddress(&p, g_qkv);  float* qkv  = (float*)p;
    cudaGetSymbolAddress(&p, g_xa);   float* xa   = (float*)p;
    cudaGetSymbolAddress(&p, g_ffin); float* ffin = (float*)p;
    cudaGetSymbolAddress(&p, g_xmlp); float* xmlp = (float*)p;
    cudaGetSymbolAddress(&p, g_b16);  f16* b16 = (f16*)p;
    cudaGetSymbolAddress(&p, g_h16);  f16* h16 = (f16*)p;
    cudaGetSymbolAddress(&p, g_w16h); f16* w16h = (f16*)p;
    cudaGetSymbolAddress(&p, g_w16l); f16* w16l = (f16*)p;

    cudaFuncSetAttribute(eb_attn_kernel,
                         cudaFuncAttributeMaxDynamicSharedMemorySize, ATTN_SMEM);
    cudaFuncSetAttribute(eb_mma_gemm<0>,
                         cudaFuncAttributeMaxDynamicSharedMemorySize, MM_SMEM);
    cudaFuncSetAttribute(eb_mma_gemm<1>,
                         cudaFuncAttributeMaxDynamicSharedMemorySize, MM_SMEM);
    cudaFuncSetAttribute(eb_mma_gemm<2>,
                         cudaFuncAttributeMaxDynamicSharedMemorySize, MM_SMEM);

    dim3 wsb(32, 8);

    // 1. LN1 -> fp16 activations
    eb_ln_kernel<1><<<TOKENS, 256>>>(x, ln1_g, ln1_b, nullptr, b16);
    // 2. QKV
    eb_wsplit_kernel<<<dim3(QKV_N / 32, DIM / 32), wsb>>>(qkv_w, w16h, w16l, DIM, QKV_N);
    eb_mma_gemm<0><<<dim3(QKV_N / 128, TOKENS / 128), 256, MM_SMEM>>>(
        b16, w16h, w16l, qkv_b, nullptr, qkv, nullptr, DIM, QKV_N);
    // 3. attention -> ctx fp16
    eb_attn_kernel<<<dim3(1024 / 64, 16 * HEADS), 128, ATTN_SMEM>>>(qkv, b16);
    // 4. proj + residual(x)
    eb_wsplit_kernel<<<dim3(DIM / 32, DIM / 32), wsb>>>(proj_w, w16h, w16l, DIM, DIM);
    eb_mma_gemm<1><<<dim3(DIM / 128, TOKENS / 128), 256, MM_SMEM>>>(
        b16, w16h, w16l, proj_b, x, xa, nullptr, DIM, DIM);
    // 5. LN2 -> ffin fp32 + fp16
    eb_ln_kernel<2><<<TOKENS, 256>>>(xa, ln2_g, ln2_b, ffin, b16);
    // 6. fc1 + GELU -> hidden fp16
    eb_wsplit_kernel<<<dim3(HIDDEN / 32, DIM / 32), wsb>>>(fc1_w, w16h, w16l, DIM, HIDDEN);
    eb_mma_gemm<2><<<dim3(HIDDEN / 128, TOKENS / 128), 256, MM_SMEM>>>(
        b16, w16h, w16l, fc1_b, nullptr, nullptr, h16, DIM, HIDDEN);
    // 7. fc2 + residual(ffin)  [reference adds the NORMALIZED tensor]
    eb_wsplit_kernel<<<dim3(DIM / 32, HIDDEN / 32), wsb>>>(fc2_w, w16h, w16l, HIDDEN, DIM);
    eb_mma_gemm<1><<<dim3(DIM / 128, TOKENS / 128), 256, MM_SMEM>>>(
        h16, w16h, w16l, fc2_b, ffin, xmlp, nullptr, HIDDEN, DIM);
    // 8. LN3 -> out
    eb_ln_kernel<0><<<TOKENS, 256>>>(xmlp, ln3_g, ln3_b, out, nullptr);
}